// round 2
// baseline (speedup 1.0000x reference)
#include <cuda_runtime.h>

// Problem shape (fixed by the dataset)
#define R_ROWS 8192
#define N_FEAT 4096
#define NP1    4097

// Packed per-feature constants: (diag_lb, diag_ub, bias_lb, bias_ub).
// float4 array => g_pack[j] is always 16B-aligned for any j.
__device__ float4 g_pack[N_FEAT];

__global__ void extract_pack_kernel(const float* __restrict__ wlb,
                                    const float* __restrict__ wub) {
    int j = blockIdx.x * blockDim.x + threadIdx.x;
    if (j < N_FEAT) {
        size_t row = (size_t)j * NP1;
        g_pack[j] = make_float4(wlb[row + j],      // diag_lb
                                wub[row + j],      // diag_ub
                                wlb[row + N_FEAT], // bias_lb
                                wub[row + N_FEAT]);// bias_ub
    }
}

// out[r,j] = v * (v>=0 ? dA[j] : dB[j])   (== relu(v)*dA - relu(-v)*dB)
// out[r,N] = sum_j v * (v>=0 ? bA[j] : bB[j]) + x[r,N]
// lb rows: (dA,dB,bA,bB) = (dl,du,bl,bu); ub rows: swapped.
__global__ __launch_bounds__(256)
void relu_backsub_kernel(const float* __restrict__ lb,
                         const float* __restrict__ ub,
                         float* __restrict__ out) {
    const int b = blockIdx.x;
    const bool is_ub = (b >= R_ROWS);
    const int r = is_ub ? (b - R_ROWS) : b;

    const float* __restrict__ x = (is_ub ? ub : lb) + (size_t)r * NP1;
    float* __restrict__ o = out + (size_t)b * NP1;

    const int t = threadIdx.x;
    // Row byte offset mod 16 is (r&3)*4 for x, and (b&3)*4 for o; since
    // b = r or r + 8192 (8192 % 4 == 0), both share the same shift.
    const int s = (4 - (r & 3)) & 3;

    float acc = 0.0f;

    // ---- scalar peel: elements [0,s) and [s+4092, 4096) -> 4 total ----
    if (t < 4) {
        const int j = (t < s) ? t : (4092 + t);
        const float v = x[j];
        const float4 pk = g_pack[j];
        const float dA = is_ub ? pk.y : pk.x;
        const float dB = is_ub ? pk.x : pk.y;
        const float bA = is_ub ? pk.w : pk.z;
        const float bB = is_ub ? pk.z : pk.w;
        o[j] = v * ((v >= 0.0f) ? dA : dB);
        acc = fmaf(v, (v >= 0.0f) ? bA : bB, acc);
    }

    // ---- vector middle: 1023 float4s covering [s, s+4092), 16B-aligned ----
    for (int i = t; i < 1023; i += 256) {
        const int j0 = s + 4 * i;
        const float4 xv = *reinterpret_cast<const float4*>(x + j0);
        float4 ov;

        {
            const float v = xv.x; const float4 pk = g_pack[j0 + 0];
            const float dA = is_ub ? pk.y : pk.x, dB = is_ub ? pk.x : pk.y;
            const float bA = is_ub ? pk.w : pk.z, bB = is_ub ? pk.z : pk.w;
            ov.x = v * ((v >= 0.0f) ? dA : dB);
            acc = fmaf(v, (v >= 0.0f) ? bA : bB, acc);
        }
        {
            const float v = xv.y; const float4 pk = g_pack[j0 + 1];
            const float dA = is_ub ? pk.y : pk.x, dB = is_ub ? pk.x : pk.y;
            const float bA = is_ub ? pk.w : pk.z, bB = is_ub ? pk.z : pk.w;
            ov.y = v * ((v >= 0.0f) ? dA : dB);
            acc = fmaf(v, (v >= 0.0f) ? bA : bB, acc);
        }
        {
            const float v = xv.z; const float4 pk = g_pack[j0 + 2];
            const float dA = is_ub ? pk.y : pk.x, dB = is_ub ? pk.x : pk.y;
            const float bA = is_ub ? pk.w : pk.z, bB = is_ub ? pk.z : pk.w;
            ov.z = v * ((v >= 0.0f) ? dA : dB);
            acc = fmaf(v, (v >= 0.0f) ? bA : bB, acc);
        }
        {
            const float v = xv.w; const float4 pk = g_pack[j0 + 3];
            const float dA = is_ub ? pk.y : pk.x, dB = is_ub ? pk.x : pk.y;
            const float bA = is_ub ? pk.w : pk.z, bB = is_ub ? pk.z : pk.w;
            ov.w = v * ((v >= 0.0f) ? dA : dB);
            acc = fmaf(v, (v >= 0.0f) ? bA : bB, acc);
        }

        *reinterpret_cast<float4*>(o + j0) = ov;
    }

    // ---- block reduction for the bias column ----
    __shared__ float red[8];
#pragma unroll
    for (int off = 16; off > 0; off >>= 1)
        acc += __shfl_down_sync(0xffffffffu, acc, off);
    if ((t & 31) == 0) red[t >> 5] = acc;
    __syncthreads();
    if (t == 0) {
        float tot = 0.0f;
#pragma unroll
        for (int i = 0; i < 8; ++i) tot += red[i];
        o[N_FEAT] = tot + x[N_FEAT];   // relu(x)-relu(-x) = x passthrough
    }
}

extern "C" void kernel_launch(void* const* d_in, const int* in_sizes, int n_in,
                              void* d_out, int out_size) {
    const float* lb  = (const float*)d_in[0];
    const float* ub  = (const float*)d_in[1];
    const float* wlb = (const float*)d_in[2];
    const float* wub = (const float*)d_in[3];
    float* out = (float*)d_out;

    extract_pack_kernel<<<(N_FEAT + 255) / 256, 256>>>(wlb, wub);
    relu_backsub_kernel<<<2 * R_ROWS, 256>>>(lb, ub, out);
}

// round 3
// speedup vs baseline: 1.1620x; 1.1620x over previous
#include <cuda_runtime.h>

#define R_ROWS 8192
#define N_FEAT 4096
#define NP1    4097
#define NVEC   1023   // float4 vectors per row body (covers features s .. s+4091)

// AoS pack for the 4-element scalar peel: (dl, du, bl, bu)
__device__ float4 g_pack[N_FEAT];

// Shift-replicated SoA float4 const arrays: g_dl4[s][i] = dl[s+4i .. s+4i+3].
// Coalesced + 16B-aligned for any row-alignment shift s in {0,1,2,3}.
__device__ float4 g_dl4[4][NVEC];
__device__ float4 g_du4[4][NVEC];
__device__ float4 g_bl4[4][NVEC];
__device__ float4 g_bu4[4][NVEC];

__global__ void extract_pack_kernel(const float* __restrict__ wlb,
                                    const float* __restrict__ wub) {
    int j = blockIdx.x * blockDim.x + threadIdx.x;
    if (j < N_FEAT) {
        size_t row = (size_t)j * NP1;
        g_pack[j] = make_float4(wlb[row + j],      // diag_lb
                                wub[row + j],      // diag_ub
                                wlb[row + N_FEAT], // bias_lb
                                wub[row + N_FEAT]);// bias_ub
    }
}

// Fill shifted SoA arrays from g_pack. 4 shifts * 4092 floats each.
__global__ void build_shifted_kernel() {
    int idx = blockIdx.x * blockDim.x + threadIdx.x;   // 0 .. 4*4092-1
    if (idx < 4 * 4 * NVEC) {
        int s   = idx / (4 * NVEC);
        int rem = idx - s * (4 * NVEC);                 // flat float index in [0,4092)
        int j   = s + rem;                              // feature index
        float4 pk = g_pack[j];
        ((float*)g_dl4)[s * 4 * NVEC + rem] = pk.x;
        ((float*)g_du4)[s * 4 * NVEC + rem] = pk.y;
        ((float*)g_bl4)[s * 4 * NVEC + rem] = pk.z;
        ((float*)g_bu4)[s * 4 * NVEC + rem] = pk.w;
    }
}

// out[r,j] = v * (v>=0 ? dA[j] : dB[j])   (== relu(v)*dA - relu(-v)*dB)
// out[r,N] = sum_j v * (v>=0 ? bA[j] : bB[j]) + x[r,N]
// lb rows: (dA,dB,bA,bB) = (dl,du,bl,bu); ub rows: swapped.
__global__ __launch_bounds__(256, 8)
void relu_backsub_kernel(const float* __restrict__ lb,
                         const float* __restrict__ ub,
                         float* __restrict__ out) {
    const int b = blockIdx.x;
    const bool is_ub = (b >= R_ROWS);
    const int r = is_ub ? (b - R_ROWS) : b;

    const float* __restrict__ x = (is_ub ? ub : lb) + (size_t)r * NP1;
    float* __restrict__ o = out + (size_t)b * NP1;

    const int t = threadIdx.x;
    // Row base misalignment: (r&3)*4 bytes (same for o since 8192 % 4 == 0).
    const int s = (4 - (r & 3)) & 3;

    const float4* __restrict__ dA = is_ub ? g_du4[s] : g_dl4[s];
    const float4* __restrict__ dB = is_ub ? g_dl4[s] : g_du4[s];
    const float4* __restrict__ bA = is_ub ? g_bu4[s] : g_bl4[s];
    const float4* __restrict__ bB = is_ub ? g_bl4[s] : g_bu4[s];

    float acc = 0.0f;

    // ---- scalar peel: elements [0,s) and [s+4092, 4096) -> 4 total ----
    if (t < 4) {
        const int j = (t < s) ? t : (4092 + t);
        const float v = x[j];
        const float4 pk = g_pack[j];
        const float da = is_ub ? pk.y : pk.x;
        const float db = is_ub ? pk.x : pk.y;
        const float ba = is_ub ? pk.w : pk.z;
        const float bb = is_ub ? pk.z : pk.w;
        o[j] = v * ((v >= 0.0f) ? da : db);
        acc = fmaf(v, (v >= 0.0f) ? ba : bb, acc);
    }

    // ---- vector body: 1023 float4s covering features [s, s+4092) ----
    for (int i = t; i < NVEC; i += 256) {
        const int j0 = s + 4 * i;
        const float4 xv = *reinterpret_cast<const float4*>(x + j0);
        const float4 vdA = dA[i];
        const float4 vdB = dB[i];
        const float4 vbA = bA[i];
        const float4 vbB = bB[i];
        float4 ov;

        ov.x = xv.x * ((xv.x >= 0.0f) ? vdA.x : vdB.x);
        acc  = fmaf(xv.x, (xv.x >= 0.0f) ? vbA.x : vbB.x, acc);
        ov.y = xv.y * ((xv.y >= 0.0f) ? vdA.y : vdB.y);
        acc  = fmaf(xv.y, (xv.y >= 0.0f) ? vbA.y : vbB.y, acc);
        ov.z = xv.z * ((xv.z >= 0.0f) ? vdA.z : vdB.z);
        acc  = fmaf(xv.z, (xv.z >= 0.0f) ? vbA.z : vbB.z, acc);
        ov.w = xv.w * ((xv.w >= 0.0f) ? vdA.w : vdB.w);
        acc  = fmaf(xv.w, (xv.w >= 0.0f) ? vbA.w : vbB.w, acc);

        *reinterpret_cast<float4*>(o + j0) = ov;
    }

    // ---- block reduction for the bias column ----
    __shared__ float red[8];
#pragma unroll
    for (int off = 16; off > 0; off >>= 1)
        acc += __shfl_down_sync(0xffffffffu, acc, off);
    if ((t & 31) == 0) red[t >> 5] = acc;
    __syncthreads();
    if (t == 0) {
        float tot = 0.0f;
#pragma unroll
        for (int i = 0; i < 8; ++i) tot += red[i];
        o[N_FEAT] = tot + x[N_FEAT];   // relu(x)-relu(-x) = x passthrough
    }
}

extern "C" void kernel_launch(void* const* d_in, const int* in_sizes, int n_in,
                              void* d_out, int out_size) {
    const float* lb  = (const float*)d_in[0];
    const float* ub  = (const float*)d_in[1];
    const float* wlb = (const float*)d_in[2];
    const float* wub = (const float*)d_in[3];
    float* out = (float*)d_out;

    extract_pack_kernel<<<(N_FEAT + 255) / 256, 256>>>(wlb, wub);
    build_shifted_kernel<<<(4 * 4 * NVEC + 255) / 256, 256>>>();
    relu_backsub_kernel<<<2 * R_ROWS, 256>>>(lb, ub, out);
}

// round 4
// speedup vs baseline: 1.6062x; 1.3823x over previous
#include <cuda_runtime.h>

#define R_ROWS 8192
#define N_FEAT 4096
#define NP1    4097
#define NVEC   1023   // float4 vectors per row body (features s .. s+4091)
#define G      8      // rows per block

// AoS pack for the scalar peel: (dl, du, bl, bu)
__device__ float4 g_pack[N_FEAT];

// Shift-replicated SoA float4 const arrays: g_dl4[s][i] = dl[s+4i .. s+4i+3].
__device__ float4 g_dl4[4][NVEC];
__device__ float4 g_du4[4][NVEC];
__device__ float4 g_bl4[4][NVEC];
__device__ float4 g_bu4[4][NVEC];

__global__ void extract_pack_kernel(const float* __restrict__ wlb,
                                    const float* __restrict__ wub) {
    int j = blockIdx.x * blockDim.x + threadIdx.x;
    if (j < N_FEAT) {
        size_t row = (size_t)j * NP1;
        g_pack[j] = make_float4(wlb[row + j],      // diag_lb
                                wub[row + j],      // diag_ub
                                wlb[row + N_FEAT], // bias_lb
                                wub[row + N_FEAT]);// bias_ub
    }
}

__global__ void build_shifted_kernel() {
    int idx = blockIdx.x * blockDim.x + threadIdx.x;   // 0 .. 4*4092-1 per shift
    if (idx < 4 * 4 * NVEC) {
        int s   = idx / (4 * NVEC);
        int rem = idx - s * (4 * NVEC);
        int j   = s + rem;
        float4 pk = g_pack[j];
        ((float*)g_dl4)[s * 4 * NVEC + rem] = pk.x;
        ((float*)g_du4)[s * 4 * NVEC + rem] = pk.y;
        ((float*)g_bl4)[s * 4 * NVEC + rem] = pk.z;
        ((float*)g_bu4)[s * 4 * NVEC + rem] = pk.w;
    }
}

// Block layout: blk in [0, 2048). Half = blk/1024 (0=lb,1=ub).
// Within half: c = shift class (0..3), p = group (0..255).
// Rows handled: r_g = c + 4*(p*G + g), g = 0..G-1 — all share alignment class c.
__global__ __launch_bounds__(256)
void relu_backsub_kernel(const float* __restrict__ lb,
                         const float* __restrict__ ub,
                         float* __restrict__ out) {
    const int blk = blockIdx.x;
    const bool is_ub = (blk >= 1024);
    const int q = is_ub ? (blk - 1024) : blk;
    const int c = q >> 8;          // alignment class
    const int p = q & 255;         // row group

    const int r0 = c + 4 * (p * G);                 // first row of the group
    const float* __restrict__ xbase = (is_ub ? ub : lb) + (size_t)r0 * NP1;
    float* __restrict__ obase = out + ((size_t)(is_ub ? R_ROWS : 0) + r0) * NP1;
    const size_t rstride = (size_t)4 * NP1;         // stride between group rows

    const int s = (4 - c) & 3;                      // (r0*NP1 + s) % 4 == 0

    const float4* __restrict__ dA = is_ub ? g_du4[s] : g_dl4[s];
    const float4* __restrict__ dB = is_ub ? g_dl4[s] : g_du4[s];
    const float4* __restrict__ bA = is_ub ? g_bu4[s] : g_bl4[s];
    const float4* __restrict__ bB = is_ub ? g_bl4[s] : g_bu4[s];

    const int t = threadIdx.x;
    float acc[G];
#pragma unroll
    for (int g = 0; g < G; ++g) acc[g] = 0.0f;

    // ---- scalar peel: 4 boundary elements per row, one warp covers all G rows ----
    if (t < 4 * G) {
        const int g = t >> 2;
        const int e = t & 3;
        const int j = (e < s) ? e : (4092 + e);
        const float v = xbase[g * rstride + j];
        const float4 pk = g_pack[j];
        const float da = is_ub ? pk.y : pk.x;
        const float db = is_ub ? pk.x : pk.y;
        const float ba = is_ub ? pk.w : pk.z;
        const float bb = is_ub ? pk.z : pk.w;
        obase[g * rstride + j] = v * ((v >= 0.0f) ? da : db);
        acc[g] = fmaf(v, (v >= 0.0f) ? ba : bb, acc[g]);
    }

    // ---- vector body: load consts once, apply to G rows ----
    for (int i = t; i < NVEC; i += 256) {
        const int j0 = s + 4 * i;
        const float4 vdA = dA[i];
        const float4 vdB = dB[i];
        const float4 vbA = bA[i];
        const float4 vbB = bB[i];

#pragma unroll
        for (int g = 0; g < G; ++g) {
            const float4 xv =
                *reinterpret_cast<const float4*>(xbase + g * rstride + j0);
            float4 ov;
            ov.x = xv.x * ((xv.x >= 0.0f) ? vdA.x : vdB.x);
            acc[g] = fmaf(xv.x, (xv.x >= 0.0f) ? vbA.x : vbB.x, acc[g]);
            ov.y = xv.y * ((xv.y >= 0.0f) ? vdA.y : vdB.y);
            acc[g] = fmaf(xv.y, (xv.y >= 0.0f) ? vbA.y : vbB.y, acc[g]);
            ov.z = xv.z * ((xv.z >= 0.0f) ? vdA.z : vdB.z);
            acc[g] = fmaf(xv.z, (xv.z >= 0.0f) ? vbA.z : vbB.z, acc[g]);
            ov.w = xv.w * ((xv.w >= 0.0f) ? vdA.w : vdB.w);
            acc[g] = fmaf(xv.w, (xv.w >= 0.0f) ? vbA.w : vbB.w, acc[g]);
            *reinterpret_cast<float4*>(obase + g * rstride + j0) = ov;
        }
    }

    // ---- block reduction: G independent sums ----
    __shared__ float red[8][G];
#pragma unroll
    for (int g = 0; g < G; ++g) {
#pragma unroll
        for (int off = 16; off > 0; off >>= 1)
            acc[g] += __shfl_down_sync(0xffffffffu, acc[g], off);
    }
    if ((t & 31) == 0) {
#pragma unroll
        for (int g = 0; g < G; ++g) red[t >> 5][g] = acc[g];
    }
    __syncthreads();
    if (t < G) {
        float tot = 0.0f;
#pragma unroll
        for (int w = 0; w < 8; ++w) tot += red[w][t];
        // passthrough last element: relu(x) - relu(-x) = x
        obase[t * rstride + N_FEAT] = tot + xbase[t * rstride + N_FEAT];
    }
}

extern "C" void kernel_launch(void* const* d_in, const int* in_sizes, int n_in,
                              void* d_out, int out_size) {
    const float* lb  = (const float*)d_in[0];
    const float* ub  = (const float*)d_in[1];
    const float* wlb = (const float*)d_in[2];
    const float* wub = (const float*)d_in[3];
    float* out = (float*)d_out;

    extract_pack_kernel<<<(N_FEAT + 255) / 256, 256>>>(wlb, wub);
    build_shifted_kernel<<<(4 * 4 * NVEC + 255) / 256, 256>>>();
    relu_backsub_kernel<<<2048, 256>>>(lb, ub, out);
}

// round 5
// speedup vs baseline: 1.6376x; 1.0195x over previous
#include <cuda_runtime.h>

#define R_ROWS 8192
#define N_FEAT 4096
#define NP1    4097
#define NVEC   1023   // float4 vectors per row body (features s .. s+4091)
#define G      8      // rows per block

// AoS pack for the scalar peel: (dl, du, bl, bu)
__device__ float4 g_pack[N_FEAT];

// Shift-replicated SoA float4 const arrays: g_dl4[s][i] = dl[s+4i .. s+4i+3].
__device__ float4 g_dl4[4][NVEC];
__device__ float4 g_du4[4][NVEC];
__device__ float4 g_bl4[4][NVEC];
__device__ float4 g_bu4[4][NVEC];

// Fused setup: thread j extracts (dl,du,bl,bu) for feature j and writes the
// AoS pack plus all shifted-SoA entries. Per (shift,array) the store index is
// j - s, stride-1 across threads -> coalesced. The 4 diagonal loads are
// scattered but MLP=4 hides the latency.
__global__ void setup_kernel(const float* __restrict__ wlb,
                             const float* __restrict__ wub) {
    const int j = blockIdx.x * blockDim.x + threadIdx.x;
    if (j >= N_FEAT) return;

    const size_t row = (size_t)j * NP1;
    const float dl = wlb[row + j];
    const float du = wub[row + j];
    const float bl = wlb[row + N_FEAT];
    const float bu = wub[row + N_FEAT];

    g_pack[j] = make_float4(dl, du, bl, bu);

    float* const fdl = (float*)g_dl4;
    float* const fdu = (float*)g_du4;
    float* const fbl = (float*)g_bl4;
    float* const fbu = (float*)g_bu4;

#pragma unroll
    for (int s = 0; s < 4; ++s) {
        const int rem = j - s;                 // position within shift-s array
        if (rem >= 0 && rem < 4 * NVEC) {
            const int base = s * 4 * NVEC + rem;
            fdl[base] = dl;
            fdu[base] = du;
            fbl[base] = bl;
            fbu[base] = bu;
        }
    }
}

// Block layout: blk in [0, 2048). Half = blk/1024 (0=lb,1=ub).
// Within half: c = shift class (0..3), p = group (0..255).
// Rows handled: r_g = c + 4*(p*G + g), g = 0..G-1 — all share alignment class c.
__global__ __launch_bounds__(256)
void relu_backsub_kernel(const float* __restrict__ lb,
                         const float* __restrict__ ub,
                         float* __restrict__ out) {
    const int blk = blockIdx.x;
    const bool is_ub = (blk >= 1024);
    const int q = is_ub ? (blk - 1024) : blk;
    const int c = q >> 8;          // alignment class
    const int p = q & 255;         // row group

    const int r0 = c + 4 * (p * G);                 // first row of the group
    const float* __restrict__ xbase = (is_ub ? ub : lb) + (size_t)r0 * NP1;
    float* __restrict__ obase = out + ((size_t)(is_ub ? R_ROWS : 0) + r0) * NP1;
    const size_t rstride = (size_t)4 * NP1;         // stride between group rows

    const int s = (4 - c) & 3;                      // (r0*NP1 + s) % 4 == 0

    const float4* __restrict__ dA = is_ub ? g_du4[s] : g_dl4[s];
    const float4* __restrict__ dB = is_ub ? g_dl4[s] : g_du4[s];
    const float4* __restrict__ bA = is_ub ? g_bu4[s] : g_bl4[s];
    const float4* __restrict__ bB = is_ub ? g_bl4[s] : g_bu4[s];

    const int t = threadIdx.x;
    float acc[G];
#pragma unroll
    for (int g = 0; g < G; ++g) acc[g] = 0.0f;

    // ---- scalar peel: 4 boundary elements per row, one warp covers all G rows ----
    if (t < 4 * G) {
        const int g = t >> 2;
        const int e = t & 3;
        const int j = (e < s) ? e : (4092 + e);
        const float v = xbase[g * rstride + j];
        const float4 pk = g_pack[j];
        const float da = is_ub ? pk.y : pk.x;
        const float db = is_ub ? pk.x : pk.y;
        const float ba = is_ub ? pk.w : pk.z;
        const float bb = is_ub ? pk.z : pk.w;
        obase[g * rstride + j] = v * ((v >= 0.0f) ? da : db);
        acc[g] = fmaf(v, (v >= 0.0f) ? ba : bb, acc[g]);
    }

    // ---- vector body: load consts once, apply to G rows ----
    for (int i = t; i < NVEC; i += 256) {
        const int j0 = s + 4 * i;
        const float4 vdA = dA[i];
        const float4 vdB = dB[i];
        const float4 vbA = bA[i];
        const float4 vbB = bB[i];

#pragma unroll
        for (int g = 0; g < G; ++g) {
            const float4 xv =
                *reinterpret_cast<const float4*>(xbase + g * rstride + j0);
            float4 ov;
            ov.x = xv.x * ((xv.x >= 0.0f) ? vdA.x : vdB.x);
            acc[g] = fmaf(xv.x, (xv.x >= 0.0f) ? vbA.x : vbB.x, acc[g]);
            ov.y = xv.y * ((xv.y >= 0.0f) ? vdA.y : vdB.y);
            acc[g] = fmaf(xv.y, (xv.y >= 0.0f) ? vbA.y : vbB.y, acc[g]);
            ov.z = xv.z * ((xv.z >= 0.0f) ? vdA.z : vdB.z);
            acc[g] = fmaf(xv.z, (xv.z >= 0.0f) ? vbA.z : vbB.z, acc[g]);
            ov.w = xv.w * ((xv.w >= 0.0f) ? vdA.w : vdB.w);
            acc[g] = fmaf(xv.w, (xv.w >= 0.0f) ? vbA.w : vbB.w, acc[g]);
            *reinterpret_cast<float4*>(obase + g * rstride + j0) = ov;
        }
    }

    // ---- block reduction: G independent sums ----
    __shared__ float red[8][G];
#pragma unroll
    for (int g = 0; g < G; ++g) {
#pragma unroll
        for (int off = 16; off > 0; off >>= 1)
            acc[g] += __shfl_down_sync(0xffffffffu, acc[g], off);
    }
    if ((t & 31) == 0) {
#pragma unroll
        for (int g = 0; g < G; ++g) red[t >> 5][g] = acc[g];
    }
    __syncthreads();
    if (t < G) {
        float tot = 0.0f;
#pragma unroll
        for (int w = 0; w < 8; ++w) tot += red[w][t];
        // passthrough last element: relu(x) - relu(-x) = x
        obase[t * rstride + N_FEAT] = tot + xbase[t * rstride + N_FEAT];
    }
}

extern "C" void kernel_launch(void* const* d_in, const int* in_sizes, int n_in,
                              void* d_out, int out_size) {
    const float* lb  = (const float*)d_in[0];
    const float* ub  = (const float*)d_in[1];
    const float* wlb = (const float*)d_in[2];
    const float* wub = (const float*)d_in[3];
    float* out = (float*)d_out;

    setup_kernel<<<(N_FEAT + 255) / 256, 256>>>(wlb, wub);
    relu_backsub_kernel<<<2048, 256>>>(lb, ub, out);
}